// round 14
// baseline (speedup 1.0000x reference)
#include <cuda_runtime.h>
#include <cuda_fp16.h>
#include <cstdint>

#define NB      16
#define CIN     256
#define COUT    256
#define HWSZ    1024
#define PT      128
#define NSTAGE  32           // 8 input channels per stage
#define NT      256          // 8 warps, 2(M) x 4(N), 64x64 warp tiles

// K layout (72 real + 8 zero-pad = 80 cols): col = k*8 + ch ; 5 x k16, no tail
#define A_STRIDE 176                 // 88 cols; 11x16B -> ldmatrix conflict-free
#define A_SZ     (128 * A_STRIDE)    // 22528
#define B_STRIDE 528                 // 256 cols + 8 pad
#define B_SZ     (80 * B_STRIDE)     // 42240
#define X_SZ     16384               // 1024 pos x 8ch x 2B fp16
#define A_OFF    0
#define B_OFF    (2 * A_SZ)          // 45056
#define X_OFF    (B_OFF + 2 * B_SZ)  // 129536
#define SMEM_DYN (X_OFF + 3 * X_SZ)  // 178688

// packed weights: [stage][80 k][256 o] fp16, rows 512B (rows 72..79 zero)
__device__ __align__(16) unsigned char g_wp[(size_t)NSTAGE * 80 * 512];
// transposed fp16 x: [n][stage][pos][8ch] = uint4 per pos
__device__ __align__(16) uint4 g_xt[(size_t)NB * NSTAGE * HWSZ];

// ---------------- helpers ----------------
__device__ __forceinline__ uint32_t smem_u32(const void* p) {
    uint32_t a;
    asm("{ .reg .u64 t; cvta.to.shared.u64 t, %1; cvt.u32.u64 %0, t; }" : "=r"(a) : "l"(p));
    return a;
}
__device__ __forceinline__ void cp16(uint32_t d, const void* g) {
    asm volatile("cp.async.cg.shared.global [%0], [%1], 16;" :: "r"(d), "l"(g));
}
#define CP_COMMIT() asm volatile("cp.async.commit_group;" ::: "memory")
#define CP_WAIT0()  asm volatile("cp.async.wait_group 0;" ::: "memory")
#define CP_WAIT1()  asm volatile("cp.async.wait_group 1;" ::: "memory")
#define CP_WAIT2()  asm volatile("cp.async.wait_group 2;" ::: "memory")

__device__ __forceinline__ void ldm_x4(uint32_t r[4], uint32_t a) {
    asm volatile("ldmatrix.sync.aligned.m8n8.x4.shared.b16 {%0,%1,%2,%3}, [%4];"
                 : "=r"(r[0]), "=r"(r[1]), "=r"(r[2]), "=r"(r[3]) : "r"(a));
}
__device__ __forceinline__ void ldm_x4_t(uint32_t r[4], uint32_t a) {
    asm volatile("ldmatrix.sync.aligned.m8n8.x4.trans.shared.b16 {%0,%1,%2,%3}, [%4];"
                 : "=r"(r[0]), "=r"(r[1]), "=r"(r[2]), "=r"(r[3]) : "r"(a));
}
__device__ __forceinline__ void mma16816(float d[4], const uint32_t a[4], const uint32_t b[2]) {
    asm volatile("mma.sync.aligned.m16n8k16.row.col.f32.f16.f16.f32 "
                 "{%0,%1,%2,%3},{%4,%5,%6,%7},{%8,%9},{%0,%1,%2,%3};"
                 : "+f"(d[0]), "+f"(d[1]), "+f"(d[2]), "+f"(d[3])
                 : "r"(a[0]), "r"(a[1]), "r"(a[2]), "r"(a[3]), "r"(b[0]), "r"(b[1]));
}

// ---------------- x transpose+cast, register-only ----------------
__global__ void prep_x(const float* __restrict__ x) {
    const int n = blockIdx.x >> 5, st = blockIdx.x & 31;
    const int t = threadIdx.x;
    const float* base = x + ((size_t)n * CIN + 8 * st) * HWSZ + 4 * t;
    float s[8][4];
    #pragma unroll
    for (int ch = 0; ch < 8; ++ch) {
        const float4 v = *(const float4*)(base + ch * HWSZ);
        s[ch][0] = v.x; s[ch][1] = v.y; s[ch][2] = v.z; s[ch][3] = v.w;
    }
    uint4* outp = g_xt + (size_t)(n * NSTAGE + st) * HWSZ + 4 * t;
    #pragma unroll
    for (int q = 0; q < 4; ++q) {
        const __half2 h01 = __floats2half2_rn(s[0][q], s[1][q]);
        const __half2 h23 = __floats2half2_rn(s[2][q], s[3][q]);
        const __half2 h45 = __floats2half2_rn(s[4][q], s[5][q]);
        const __half2 h67 = __floats2half2_rn(s[6][q], s[7][q]);
        uint4 v;
        v.x = *(const uint32_t*)&h01;
        v.y = *(const uint32_t*)&h23;
        v.z = *(const uint32_t*)&h45;
        v.w = *(const uint32_t*)&h67;
        outp[q] = v;
    }
}

// ---------------- weight prep: coalesced reads, smem transpose, 80 rows ----------------
__global__ void prep_weights(const float* __restrict__ weight) {
    __shared__ __align__(16) __half s_w[80][264];    // odd 16B stride
    const int s = blockIdx.x;                        // 32 blocks
    const int o = threadIdx.x;                       // 256 threads
    float f[72];
    const float4* src = (const float4*)(weight + (size_t)o * 2304 + s * 72);
    #pragma unroll
    for (int q = 0; q < 18; ++q) *(float4*)(f + 4 * q) = src[q];
    #pragma unroll
    for (int ch = 0; ch < 8; ++ch)
        #pragma unroll
        for (int k = 0; k < 9; ++k)
            s_w[k * 8 + ch][o] = __float2half(f[ch * 9 + k]);
    #pragma unroll
    for (int r = 72; r < 80; ++r) s_w[r][o] = __float2half(0.f);
    __syncthreads();
    unsigned char* dst = g_wp + (size_t)s * (80 * 512);
    #pragma unroll
    for (int r = 0; r < 20; ++r) {
        const int idx = threadIdx.x + r * 256;       // 5120 uint2
        const int kcol = idx >> 6, oc = idx & 63;
        *(uint2*)(dst + kcol * 512 + oc * 8) = *(const uint2*)&s_w[kcol][4 * oc];
    }
}

// ---------------- main kernel ----------------
__global__ __launch_bounds__(NT, 1)
void dcn_mma_kernel(const float* __restrict__ x,
                    const float* __restrict__ offset,
                    float* __restrict__ out)
{
    extern __shared__ char sm[];
    const uint32_t sb = smem_u32(sm);

    const int tid  = threadIdx.x;
    const int wid  = tid >> 5, lane = tid & 31;
    const int n    = blockIdx.y;
    const int p0   = blockIdx.x * PT;
    const int warpM = wid & 1;            // 2 M-tiles of 64
    const int warpN = (wid >> 1) & 3;     // 4 N-tiles of 64
    const int pbit  = (wid >> 2) & 1;     // SMSP-paired warps opposite order

    // zero A pad cols 72..79 (bytes 144..159) of both buffers
    if (tid < 256) {
        uint4 z = make_uint4(0, 0, 0, 0);
        *(uint4*)(sm + A_OFF + (tid >> 7) * A_SZ + (tid & 127) * A_STRIDE + 144) = z;
    }

    // ---- sampling tables -> registers (5 entries/thread) ----
    uint32_t tlo[5], thi[5];
    float4 twt[5];
    #pragma unroll
    for (int e = 0; e < 5; ++e) {
        const int j = tid + e * NT;
        if (j < 9 * PT) {
            const int k = j >> 7, p = j & 127;
            const int gp = p0 + p;
            const float2 d2 = *reinterpret_cast<const float2*>(
                offset + ((size_t)n * HWSZ + gp) * 18 + 2 * k);
            const float py = (float)(gp >> 5) + (float)(k / 3 - 1) + d2.x;
            const float px = (float)(gp & 31) + (float)(k % 3 - 1) + d2.y;
            const float y0 = floorf(py), x0 = floorf(px);
            const float ly = py - y0, lx = px - x0;
            const float hy = 1.f - ly, hx = 1.f - lx;
            const float vy0 = (y0 >= 0.f && y0 <= 31.f) ? 1.f : 0.f;
            const float vy1 = (y0 >= -1.f && y0 <= 30.f) ? 1.f : 0.f;
            const float vx0 = (x0 >= 0.f && x0 <= 31.f) ? 1.f : 0.f;
            const float vx1 = (x0 >= -1.f && x0 <= 30.f) ? 1.f : 0.f;
            const uint32_t iy0 = (uint32_t)(int)fminf(fmaxf(y0, 0.f), 31.f);
            const uint32_t iy1 = (uint32_t)(int)fminf(fmaxf(y0 + 1.f, 0.f), 31.f);
            const uint32_t ix0 = (uint32_t)(int)fminf(fmaxf(x0, 0.f), 31.f);
            const uint32_t ix1 = (uint32_t)(int)fminf(fmaxf(x0 + 1.f, 0.f), 31.f);
            tlo[e] = (iy0 * 32 + ix0) | ((iy0 * 32 + ix1) << 16);
            thi[e] = (iy1 * 32 + ix0) | ((iy1 * 32 + ix1) << 16);
            twt[e] = make_float4(hy * hx * vy0 * vx0, hy * lx * vy0 * vx1,
                                 ly * hx * vy1 * vx0, ly * lx * vy1 * vx1);
        } else {
            tlo[e] = thi[e] = 0;
            twt[e] = make_float4(0.f, 0.f, 0.f, 0.f);
        }
    }

    // ---- async staging ----
    auto issue_b = [&](int st) {   // 2560 x 16B = 10/thread
        const char* gsrc = (const char*)g_wp + (size_t)st * (80 * 512);
        const uint32_t bdst = sb + B_OFF + (st & 1) * B_SZ;
        #pragma unroll
        for (int q = 0; q < 10; ++q) {
            const int idx = tid + q * NT;
            const int row = idx >> 5, ch = idx & 31;
            cp16(bdst + row * B_STRIDE + ch * 16, gsrc + row * 512 + ch * 16);
        }
    };
    auto issue_x = [&](int st) {   // 16KB = 4/thread
        const uint32_t xd = sb + X_OFF + (st % 3) * X_SZ;
        const char* gs = (const char*)(g_xt + (size_t)(n * NSTAGE + st) * HWSZ);
        #pragma unroll
        for (int q = 0; q < 4; ++q)
            cp16(xd + (tid + q * NT) * 16, gs + (tid + q * NT) * 16);
    };

    // ---- build deformed fp16 A tile ----
    auto build_a = [&](int st) {
        const uint4* xp = (const uint4*)(sm + X_OFF + (st % 3) * X_SZ);
        char* abuf = sm + A_OFF + (st & 1) * A_SZ;
        #pragma unroll
        for (int e = 0; e < 5; ++e) {
            const int j = tid + e * NT;
            if (e == 4 && j >= 9 * PT) break;
            const int k = j >> 7, p = j & 127;
            uint4 c00 = xp[tlo[e] & 0xFFFF];
            uint4 c01 = xp[tlo[e] >> 16];
            uint4 c10 = xp[thi[e] & 0xFFFF];
            uint4 c11 = xp[thi[e] >> 16];
            const float4 w = twt[e];
            uint4 r;
            const uint32_t* p00 = &c00.x;
            const uint32_t* p01 = &c01.x;
            const uint32_t* p10 = &c10.x;
            const uint32_t* p11 = &c11.x;
            uint32_t* pr = &r.x;
            #pragma unroll
            for (int q = 0; q < 4; ++q) {
                const float2 f00 = __half22float2(*(const __half2*)&p00[q]);
                const float2 f01 = __half22float2(*(const __half2*)&p01[q]);
                const float2 f10 = __half22float2(*(const __half2*)&p10[q]);
                const float2 f11 = __half22float2(*(const __half2*)&p11[q]);
                const float va = w.x * f00.x + w.y * f01.x + w.z * f10.x + w.w * f11.x;
                const float vb = w.x * f00.y + w.y * f01.y + w.z * f10.y + w.w * f11.y;
                const __half2 h = __floats2half2_rn(va, vb);
                pr[q] = *(const uint32_t*)&h;
            }
            *(uint4*)(abuf + p * A_STRIDE + k * 16) = r;
        }
    };

    // ---- accumulators: 4 m16 x 8 n8 ----
    float acc[4][8][4];
    #pragma unroll
    for (int i = 0; i < 4; ++i)
        #pragma unroll
        for (int j = 0; j < 8; ++j)
            #pragma unroll
            for (int q = 0; q < 4; ++q) acc[i][j][q] = 0.f;

    const uint32_t aRowOff = (uint32_t)(warpM * 64 + (lane & 15)) * A_STRIDE
                           + (uint32_t)(lane >> 4) * 16;
    const uint32_t bRowOff = (uint32_t)(lane & 15) * B_STRIDE
                           + (uint32_t)(warpN * 128) + (uint32_t)(lane >> 4) * 16;

    // ---- software-pipelined MMA: A double-buffered across kc, B batched per kc ----
    auto mma_stage = [&](int st) {
        const uint32_t ab = sb + A_OFF + (st & 1) * A_SZ;
        const uint32_t bb = sb + B_OFF + (st & 1) * B_SZ;
        uint32_t a[2][4][4];
        #pragma unroll
        for (int mi = 0; mi < 4; ++mi)
            ldm_x4(a[0][mi], ab + aRowOff + mi * 16 * A_STRIDE);
        #pragma unroll
        for (int kc = 0; kc < 5; ++kc) {
            const int cur = kc & 1;
            if (kc < 4) {
                #pragma unroll
                for (int mi = 0; mi < 4; ++mi)
                    ldm_x4(a[cur ^ 1][mi],
                           ab + aRowOff + mi * 16 * A_STRIDE + (kc + 1) * 32);
            }
            uint32_t b[4][4];
            #pragma unroll
            for (int jt = 0; jt < 4; ++jt)
                ldm_x4_t(b[jt], bb + bRowOff + kc * 16 * B_STRIDE + jt * 32);
            #pragma unroll
            for (int jt = 0; jt < 4; ++jt)
                #pragma unroll
                for (int mi = 0; mi < 4; ++mi) {
                    mma16816(acc[mi][2 * jt],     a[cur][mi], b[jt]);
                    mma16816(acc[mi][2 * jt + 1], a[cur][mi], b[jt] + 2);
                }
        }
    };

    // ---- prologue: x(0), x(1), B(0) ----
    issue_x(0);
    issue_x(1);
    issue_b(0);
    CP_COMMIT();
    CP_WAIT0();
    __syncthreads();
    build_a(0);
    __syncthreads();

    // ---- main loop ----
    #pragma unroll 1
    for (int s = 0; s < NSTAGE; ++s) {
        const bool more = (s + 1 < NSTAGE);
        if (more) issue_b(s + 1);
        CP_COMMIT();                           // group: B(s+1)
        if (s + 2 < NSTAGE) issue_x(s + 2);
        CP_COMMIT();                           // group: x(s+2)
        CP_WAIT2();                            // x(s+1) landed before build
        if (pbit) {
            if (more) build_a(s + 1);
            mma_stage(s);
        } else {
            mma_stage(s);
            if (more) build_a(s + 1);
        }
        CP_WAIT1();                            // B(s+1) landed; x(s+2) may fly
        __syncthreads();
    }

    // ---- epilogue ----
    const int pbase = p0 + warpM * 64 + (lane >> 2);
    const int obase = warpN * 64 + (lane & 3) * 2;
    float* ob = out + (size_t)n * COUT * HWSZ;
    #pragma unroll
    for (int mt = 0; mt < 4; ++mt) {
        #pragma unroll
        for (int j = 0; j < 8; ++j) {
            const int o = obase + j * 8;
            const int p = pbase + mt * 16;
            ob[(size_t)o * HWSZ + p]           = acc[mt][j][0];
            ob[(size_t)(o + 1) * HWSZ + p]     = acc[mt][j][1];
            ob[(size_t)o * HWSZ + p + 8]       = acc[mt][j][2];
            ob[(size_t)(o + 1) * HWSZ + p + 8] = acc[mt][j][3];
        }
    }
}

extern "C" void kernel_launch(void* const* d_in, const int* in_sizes, int n_in,
                              void* d_out, int out_size)
{
    const float* x      = (const float*)d_in[0];
    const float* offset = (const float*)d_in[1];
    const float* weight = (const float*)d_in[2];
    float* out          = (float*)d_out;

    static int smem_set = 0;
    if (!smem_set) {
        cudaFuncSetAttribute(dcn_mma_kernel,
                             cudaFuncAttributeMaxDynamicSharedMemorySize, SMEM_DYN);
        smem_set = 1;
    }

    prep_x<<<NB * NSTAGE, 256>>>(x);
    prep_weights<<<NSTAGE, 256>>>(weight);
    dim3 grid(HWSZ / PT, NB);                 // 8 x 16 = 128 blocks, one wave
    dcn_mma_kernel<<<grid, NT, SMEM_DYN>>>(x, offset, out);
}

// round 15
// speedup vs baseline: 1.0905x; 1.0905x over previous
#include <cuda_runtime.h>
#include <cuda_fp16.h>
#include <cstdint>

#define NB      16
#define CIN     256
#define COUT    256
#define HWSZ    1024
#define PT      128
#define NSTAGE  32           // 8 input channels per stage
#define NT      256          // 8 warps, 2(M) x 4(N), 64x64 warp tiles

// K layout (72 real + 8 zero-pad = 80 cols): col = ktap*8 + ch ; 5 x k16
#define A_STRIDE 176                 // 88 cols; 11x16B -> ldmatrix conflict-free
#define A_SZ     (128 * A_STRIDE)    // 22528 ; 2 buffers = 45056 (static smem)

// fragment-ordered weights: [stage][kc(5)][nb2(16)][lane(32)] uint4
__device__ __align__(16) uint4 g_wf[(size_t)NSTAGE * 5 * 16 * 32];
// transposed fp16 x: [n][stage][pos][8ch] = uint4 per pos
__device__ __align__(16) uint4 g_xt[(size_t)NB * NSTAGE * HWSZ];

// ---------------- helpers ----------------
__device__ __forceinline__ uint32_t smem_u32(const void* p) {
    uint32_t a;
    asm("{ .reg .u64 t; cvta.to.shared.u64 t, %1; cvt.u32.u64 %0, t; }" : "=r"(a) : "l"(p));
    return a;
}
__device__ __forceinline__ void ldm_x4(uint32_t r[4], uint32_t a) {
    asm volatile("ldmatrix.sync.aligned.m8n8.x4.shared.b16 {%0,%1,%2,%3}, [%4];"
                 : "=r"(r[0]), "=r"(r[1]), "=r"(r[2]), "=r"(r[3]) : "r"(a));
}
__device__ __forceinline__ void mma16816(float d[4], const uint32_t a[4], const uint32_t b[2]) {
    asm volatile("mma.sync.aligned.m16n8k16.row.col.f32.f16.f16.f32 "
                 "{%0,%1,%2,%3},{%4,%5,%6,%7},{%8,%9},{%0,%1,%2,%3};"
                 : "+f"(d[0]), "+f"(d[1]), "+f"(d[2]), "+f"(d[3])
                 : "r"(a[0]), "r"(a[1]), "r"(a[2]), "r"(a[3]), "r"(b[0]), "r"(b[1]));
}

// ---------------- x transpose+cast, register-only ----------------
__global__ void prep_x(const float* __restrict__ x) {
    const int n = blockIdx.x >> 5, st = blockIdx.x & 31;
    const int t = threadIdx.x;
    const float* base = x + ((size_t)n * CIN + 8 * st) * HWSZ + 4 * t;
    float s[8][4];
    #pragma unroll
    for (int ch = 0; ch < 8; ++ch) {
        const float4 v = *(const float4*)(base + ch * HWSZ);
        s[ch][0] = v.x; s[ch][1] = v.y; s[ch][2] = v.z; s[ch][3] = v.w;
    }
    uint4* outp = g_xt + (size_t)(n * NSTAGE + st) * HWSZ + 4 * t;
    #pragma unroll
    for (int q = 0; q < 4; ++q) {
        const __half2 h01 = __floats2half2_rn(s[0][q], s[1][q]);
        const __half2 h23 = __floats2half2_rn(s[2][q], s[3][q]);
        const __half2 h45 = __floats2half2_rn(s[4][q], s[5][q]);
        const __half2 h67 = __floats2half2_rn(s[6][q], s[7][q]);
        uint4 v;
        v.x = *(const uint32_t*)&h01;
        v.y = *(const uint32_t*)&h23;
        v.z = *(const uint32_t*)&h45;
        v.w = *(const uint32_t*)&h67;
        outp[q] = v;
    }
}

// ---------------- weight prep -> per-lane mma fragment order ----------------
__global__ void prep_weights(const float* __restrict__ weight) {
    __shared__ __align__(16) __half s_w[80][264];    // [kcol][o], odd 16B stride
    const int s = blockIdx.x;                        // 32 blocks
    const int o = threadIdx.x;                       // 256 threads
    float f[72];
    const float4* src = (const float4*)(weight + (size_t)o * 2304 + s * 72);
    #pragma unroll
    for (int q = 0; q < 18; ++q) *(float4*)(f + 4 * q) = src[q];
    #pragma unroll
    for (int ch = 0; ch < 8; ++ch)
        #pragma unroll
        for (int k = 0; k < 9; ++k)
            s_w[k * 8 + ch][o] = __float2half(f[ch * 9 + k]);
    #pragma unroll
    for (int r = 72; r < 80; ++r) s_w[r][o] = __float2half(0.f);
    __syncthreads();

    // emit fragments: lane l of (kc, nb2) holds B[k0..k0+1, k0+8..k0+9][n0, n0+8]
    uint4* dst = g_wf + (size_t)s * (5 * 16 * 32);
    #pragma unroll
    for (int r = 0; r < 10; ++r) {
        const int idx  = threadIdx.x + r * 256;      // 0..2559
        const int lane = idx & 31;
        const int nb2  = (idx >> 5) & 15;
        const int kc   = idx >> 9;
        const int n0 = nb2 * 16 + (lane >> 2);
        const int k0 = kc * 16 + (lane & 3) * 2;
        uint4 v;
        v.x = ((uint32_t)*(unsigned short*)&s_w[k0 + 1][n0] << 16) | *(unsigned short*)&s_w[k0][n0];
        v.y = ((uint32_t)*(unsigned short*)&s_w[k0 + 9][n0] << 16) | *(unsigned short*)&s_w[k0 + 8][n0];
        v.z = ((uint32_t)*(unsigned short*)&s_w[k0 + 1][n0 + 8] << 16) | *(unsigned short*)&s_w[k0][n0 + 8];
        v.w = ((uint32_t)*(unsigned short*)&s_w[k0 + 9][n0 + 8] << 16) | *(unsigned short*)&s_w[k0 + 8][n0 + 8];
        dst[idx] = v;
    }
}

// ---------------- main kernel ----------------
__global__ __launch_bounds__(NT, 1)
void dcn_mma_kernel(const float* __restrict__ x,
                    const float* __restrict__ offset,
                    float* __restrict__ out)
{
    __shared__ __align__(16) char sm[2 * A_SZ];      // A double buffer only
    const uint32_t sb = smem_u32(sm);

    const int tid  = threadIdx.x;
    const int wid  = tid >> 5, lane = tid & 31;
    const int n    = blockIdx.y;
    const int p0   = blockIdx.x * PT;
    const int warpM = wid & 1;            // 2 M-tiles of 64
    const int warpN = (wid >> 1) & 3;     // 4 N-tiles of 64
    const int pbit  = (wid >> 2) & 1;     // SMSP-paired warps opposite order

    // zero A pad cols 72..79 (bytes 144..159) of both buffers
    if (tid < 256) {
        uint4 z = make_uint4(0, 0, 0, 0);
        *(uint4*)(sm + (tid >> 7) * A_SZ + (tid & 127) * A_STRIDE + 144) = z;
    }

    // ---- sampling tables -> registers (5 entries/thread) ----
    uint32_t tlo[5], thi[5];
    float4 twt[5];
    #pragma unroll
    for (int e = 0; e < 5; ++e) {
        const int j = tid + e * NT;
        if (j < 9 * PT) {
            const int k = j >> 7, p = j & 127;
            const int gp = p0 + p;
            const float2 d2 = *reinterpret_cast<const float2*>(
                offset + ((size_t)n * HWSZ + gp) * 18 + 2 * k);
            const float py = (float)(gp >> 5) + (float)(k / 3 - 1) + d2.x;
            const float px = (float)(gp & 31) + (float)(k % 3 - 1) + d2.y;
            const float y0 = floorf(py), x0 = floorf(px);
            const float ly = py - y0, lx = px - x0;
            const float hy = 1.f - ly, hx = 1.f - lx;
            const float vy0 = (y0 >= 0.f && y0 <= 31.f) ? 1.f : 0.f;
            const float vy1 = (y0 >= -1.f && y0 <= 30.f) ? 1.f : 0.f;
            const float vx0 = (x0 >= 0.f && x0 <= 31.f) ? 1.f : 0.f;
            const float vx1 = (x0 >= -1.f && x0 <= 30.f) ? 1.f : 0.f;
            const uint32_t iy0 = (uint32_t)(int)fminf(fmaxf(y0, 0.f), 31.f);
            const uint32_t iy1 = (uint32_t)(int)fminf(fmaxf(y0 + 1.f, 0.f), 31.f);
            const uint32_t ix0 = (uint32_t)(int)fminf(fmaxf(x0, 0.f), 31.f);
            const uint32_t ix1 = (uint32_t)(int)fminf(fmaxf(x0 + 1.f, 0.f), 31.f);
            tlo[e] = (iy0 * 32 + ix0) | ((iy0 * 32 + ix1) << 16);
            thi[e] = (iy1 * 32 + ix0) | ((iy1 * 32 + ix1) << 16);
            twt[e] = make_float4(hy * hx * vy0 * vx0, hy * lx * vy0 * vx1,
                                 ly * hx * vy1 * vx0, ly * lx * vy1 * vx1);
        } else {
            tlo[e] = thi[e] = 0;
            twt[e] = make_float4(0.f, 0.f, 0.f, 0.f);
        }
    }

    // ---- build deformed fp16 A tile: 4 random LDG.128 (L1-hit) + 1 STS.128 ----
    auto build_a = [&](int st) {
        const uint4* __restrict__ xp = g_xt + (size_t)(n * NSTAGE + st) * HWSZ;
        char* abuf = sm + (st & 1) * A_SZ;
        #pragma unroll
        for (int e = 0; e < 5; ++e) {
            const int j = tid + e * NT;
            if (e == 4 && j >= 9 * PT) break;
            const int k = j >> 7, p = j & 127;
            const uint4 c00 = __ldg(xp + (tlo[e] & 0xFFFF));
            const uint4 c01 = __ldg(xp + (tlo[e] >> 16));
            const uint4 c10 = __ldg(xp + (thi[e] & 0xFFFF));
            const uint4 c11 = __ldg(xp + (thi[e] >> 16));
            const float4 w = twt[e];
            uint4 r;
            const uint32_t* p00 = &c00.x;
            const uint32_t* p01 = &c01.x;
            const uint32_t* p10 = &c10.x;
            const uint32_t* p11 = &c11.x;
            uint32_t* pr = &r.x;
            #pragma unroll
            for (int q = 0; q < 4; ++q) {
                const float2 f00 = __half22float2(*(const __half2*)&p00[q]);
                const float2 f01 = __half22float2(*(const __half2*)&p01[q]);
                const float2 f10 = __half22float2(*(const __half2*)&p10[q]);
                const float2 f11 = __half22float2(*(const __half2*)&p11[q]);
                const float va = w.x * f00.x + w.y * f01.x + w.z * f10.x + w.w * f11.x;
                const float vb = w.x * f00.y + w.y * f01.y + w.z * f10.y + w.w * f11.y;
                const __half2 h = __floats2half2_rn(va, vb);
                pr[q] = *(const uint32_t*)&h;
            }
            *(uint4*)(abuf + p * A_STRIDE + k * 16) = r;
        }
    };

    // ---- accumulators: 4 m16 x 8 n8 ----
    float acc[4][8][4];
    #pragma unroll
    for (int i = 0; i < 4; ++i)
        #pragma unroll
        for (int j = 0; j < 8; ++j)
            #pragma unroll
            for (int q = 0; q < 4; ++q) acc[i][j][q] = 0.f;

    const uint32_t aRowOff = (uint32_t)(warpM * 64 + (lane & 15)) * A_STRIDE
                           + (uint32_t)(lane >> 4) * 16;

    // ---- MMA stage: A via ldmatrix, B fragments via direct LDG ----
    auto mma_stage = [&](int st) {
        const uint32_t ab = sb + (st & 1) * A_SZ;
        const uint4* __restrict__ wf =
            g_wf + (size_t)st * (5 * 16 * 32) + (warpN * 4) * 32 + lane;
        #pragma unroll
        for (int kc = 0; kc < 5; ++kc) {
            uint32_t a[4][4];
            #pragma unroll
            for (int mi = 0; mi < 4; ++mi)
                ldm_x4(a[mi], ab + aRowOff + mi * 16 * A_STRIDE + kc * 32);
            #pragma unroll
            for (int jt = 0; jt < 4; ++jt) {
                const uint4 bv = __ldg(wf + (kc * 16 + jt) * 32);
                #pragma unroll
                for (int mi = 0; mi < 4; ++mi) {
                    mma16816(acc[mi][2 * jt],     a[mi], &bv.x);
                    mma16816(acc[mi][2 * jt + 1], a[mi], &bv.z);
                }
            }
        }
    };

    // ---- prologue ----
    __syncthreads();          // pad zeroing visible
    build_a(0);
    __syncthreads();

    // ---- main loop: one barrier per stage ----
    #pragma unroll 1
    for (int s = 0; s < NSTAGE; ++s) {
        const bool more = (s + 1 < NSTAGE);
        if (pbit) {
            if (more) build_a(s + 1);
            mma_stage(s);
        } else {
            mma_stage(s);
            if (more) build_a(s + 1);
        }
        __syncthreads();
    }

    // ---- epilogue ----
    const int pbase = p0 + warpM * 64 + (lane >> 2);
    const int obase = warpN * 64 + (lane & 3) * 2;
    float* ob = out + (size_t)n * COUT * HWSZ;
    #pragma unroll
    for (int mt = 0; mt < 4; ++mt) {
        #pragma unroll
        for (int j = 0; j < 8; ++j) {
            const int o = obase + j * 8;
            const int p = pbase + mt * 16;
            ob[(size_t)o * HWSZ + p]           = acc[mt][j][0];
            ob[(size_t)(o + 1) * HWSZ + p]     = acc[mt][j][1];
            ob[(size_t)o * HWSZ + p + 8]       = acc[mt][j][2];
            ob[(size_t)(o + 1) * HWSZ + p + 8] = acc[mt][j][3];
        }
    }
}

extern "C" void kernel_launch(void* const* d_in, const int* in_sizes, int n_in,
                              void* d_out, int out_size)
{
    const float* x      = (const float*)d_in[0];
    const float* offset = (const float*)d_in[1];
    const float* weight = (const float*)d_in[2];
    float* out          = (float*)d_out;

    prep_x<<<NB * NSTAGE, 256>>>(x);
    prep_weights<<<NSTAGE, 256>>>(weight);
    dim3 grid(HWSZ / PT, NB);                 // 8 x 16 = 128 blocks, one wave
    dcn_mma_kernel<<<grid, NT>>>(x, offset, out);
}